// round 14
// baseline (speedup 1.0000x reference)
#include <cuda_runtime.h>
#include <cuda_bf16.h>
#include <cstdint>

// ---------------- problem constants ----------------
#define BB 16384
#define DD 1024
#define HH 1024
#define KK 2048          // D + H concatenated reduction dim
#define G5 5120          // 5 * H gate rows
#define OUT_C_OFF ((size_t)BB * HH)

// ---------------- GEMM tiling (tf32) ----------------
#define BM 256           // batch rows per CTA
#define BHW 32           // h columns per CTA (per gate)
#define BN 160           // 5 gates * 32 h
#define BK 32            // K elements per pipeline stage (128 B f32 per row)
#define NSTAGE (KK / BK) // 64
#define STAGES 2
#define NTHREADS 512     // 16 warps: 4(M) x 4(N), warp tile 64 x 40

// SMEM row: 128B data + 64B pad -> rows offset 64 mod 128 => conflict-free LDS.128
#define ROWSTR 192
#define SA_STAGE (BM * ROWSTR)             // 49152
#define SB_STAGE (BN * ROWSTR)             // 30720
#define SA_OFF(s) ((s) * SA_STAGE)
#define SB_OFF(s) (STAGES * SA_STAGE + (s) * SB_STAGE)
#define PIPE_BYTES (STAGES * (SA_STAGE + SB_STAGE))      // 159744
// epilogue gate buffer [5][256][34] floats (174080 B) overlays pipeline region
#define GSTR 34
#define GATES_BYTES (5 * BM * GSTR * 4)    // 174080
#define SM_BIAS GATES_BYTES                // 160 floats after gate buffer
#define SMEM_TOTAL (GATES_BYTES + 1024)    // 175104  (< 227KB cap)

// ---------------- device scratch (allocation-free) ----------------
// k-dimension stored PERMUTED within each 16-k block:
//   stored position p holds original k = (p&3)*4 + (p>>2)
// so positions 4*lt .. 4*lt+3 hold original k {lt, lt+4, lt+8, lt+12}
__device__ float g_A[(size_t)BB * KK];   // 134 MB  [x | h_prev], tf32-rounded f32
__device__ float g_W[(size_t)G5 * KK];   //  42 MB  [Wx | Uh],    tf32-rounded f32
__device__ float g_bias[G5];

// ---------------- PTX helpers (base-target only: sm_80+) ----------------
__device__ __forceinline__ void cpasync16(uint32_t dst, const void* src) {
    asm volatile("cp.async.cg.shared.global [%0], [%1], 16;" :: "r"(dst), "l"(src) : "memory");
}
__device__ __forceinline__ void cp_commit() {
    asm volatile("cp.async.commit_group;" ::: "memory");
}
template <int N>
__device__ __forceinline__ void cp_wait() {
    asm volatile("cp.async.wait_group %0;" :: "n"(N) : "memory");
}
__device__ __forceinline__ uint32_t smem_u32(const void* p) {
    uint32_t a;
    asm("{ .reg .u64 t; cvta.to.shared.u64 t, %1; cvt.u32.u64 %0, t; }" : "=r"(a) : "l"(p));
    return a;
}
// round-to-nearest tf32 (clears low 13 mantissa bits with rna rounding)
__device__ __forceinline__ float rna_tf32(float x) {
    uint32_t u;
    asm("cvt.rna.tf32.f32 %0, %1;" : "=r"(u) : "f"(x));
    return __uint_as_float(u);
}
__device__ __forceinline__ void mma_tf32(float* d,
                                         float a0, float a1, float a2, float a3,
                                         float b0, float b1) {
    asm volatile(
        "mma.sync.aligned.m16n8k8.row.col.f32.tf32.tf32.f32 "
        "{%0,%1,%2,%3}, {%4,%5,%6,%7}, {%8,%9}, {%0,%1,%2,%3};"
        : "+f"(d[0]), "+f"(d[1]), "+f"(d[2]), "+f"(d[3])
        : "r"(__float_as_uint(a0)), "r"(__float_as_uint(a1)),
          "r"(__float_as_uint(a2)), "r"(__float_as_uint(a3)),
          "r"(__float_as_uint(b0)), "r"(__float_as_uint(b1)));
}
__device__ __forceinline__ float sigf(float v) { return 1.0f / (1.0f + __expf(-v)); }

// ---------------- convert kernels (concat + rna round + k16 permute) ----------------
__global__ void conv_A(const float* __restrict__ x, const float* __restrict__ hp) {
    int gid = blockIdx.x * blockDim.x + threadIdx.x;   // BB*512 threads, float4 each
    int b = gid >> 9, rem = gid & 511;
    const float* src = (rem < 256) ? (x + (size_t)b * 1024 + rem * 4)
                                   : (hp + (size_t)b * 1024 + (rem - 256) * 4);
    float4 v = *(const float4*)src;
    float* dst = g_A + (size_t)b * KK + ((rem >> 2) << 4) + (rem & 3);
    dst[0]  = rna_tf32(v.x);
    dst[4]  = rna_tf32(v.y);
    dst[8]  = rna_tf32(v.z);
    dst[12] = rna_tf32(v.w);
}
__global__ void conv_W(const float* __restrict__ Wx, const float* __restrict__ Uh) {
    int gid = blockIdx.x * blockDim.x + threadIdx.x;   // G5*512 threads
    int r = gid >> 9, rem = gid & 511;
    const float* src = (rem < 256) ? (Wx + (size_t)r * 1024 + rem * 4)
                                   : (Uh + (size_t)r * 1024 + (rem - 256) * 4);
    float4 v = *(const float4*)src;
    float* dst = g_W + (size_t)r * KK + ((rem >> 2) << 4) + (rem & 3);
    dst[0]  = rna_tf32(v.x);
    dst[4]  = rna_tf32(v.y);
    dst[8]  = rna_tf32(v.z);
    dst[12] = rna_tf32(v.w);
}
__global__ void conv_bias(const float* __restrict__ bx, const float* __restrict__ bh) {
    int i = blockIdx.x * blockDim.x + threadIdx.x;
    if (i < G5) g_bias[i] = bx[i] + bh[i];
}

// ---------------- fused GEMM (mma.sync tf32) + LSTM epilogue ----------------
__global__ void __launch_bounds__(NTHREADS, 1)
lstm_gemm(const float* __restrict__ c_prev, const float* __restrict__ dynw,
          float* __restrict__ out) {
    extern __shared__ char smem[];
    const uint32_t sb = smem_u32(smem);
    const int tid  = threadIdx.x;
    const int wid  = tid >> 5;
    const int lane = tid & 31;
    const int h0 = blockIdx.x * BHW;     // 32 h-blocks (x fastest -> A-tile L2 reuse)
    const int m0 = blockIdx.y * BM;      // 64 m-blocks

    // warp grid 4(M) x 4(N): warp tile 64 x 40
    const int wm = (wid >> 2) * 64;
    const int wn = (wid & 3) * 40;
    const int lg = lane >> 2;            // fragment row group 0..7
    const int lt = lane & 3;             // fragment k selector 0..3

    // bias staging (region beyond gate buffer)
    float* bias_s = (float*)(smem + SM_BIAS);
    if (tid < BN) bias_s[tid] = g_bias[(tid >> 5) * 1024 + h0 + (tid & 31)];

    // ---- per-thread cp.async assignments (fixed across stages)
    // A: 256 rows x 8 chunks(16B) = 2048 -> 4 per thread
    int ar[4], ac[4];
    const float* a_src[4];
#pragma unroll
    for (int i = 0; i < 4; i++) {
        int q = tid + i * 512;
        ar[i] = q >> 3; ac[i] = q & 7;
        a_src[i] = g_A + (size_t)(m0 + ar[i]) * KK + ac[i] * 4;
    }
    // B: 160 rows x 8 chunks = 1280 -> 2 per thread + 1 extra for tid<256
    int br[3], bc[3];
    const float* b_src[3];
#pragma unroll
    for (int i = 0; i < 3; i++) {
        int q = tid + i * 512;
        if (q < 1280) {
            br[i] = q >> 3; bc[i] = q & 7;
            b_src[i] = g_W + (size_t)((br[i] >> 5) * 1024 + h0 + (br[i] & 31)) * KK + bc[i] * 4;
        } else { br[i] = 0; bc[i] = 0; b_src[i] = nullptr; }
    }

    auto issue_stage = [&](int s) {
        const int buf = s & 1;
        const int kofs = s * BK;
#pragma unroll
        for (int i = 0; i < 4; i++)
            cpasync16(sb + SA_OFF(buf) + ar[i] * ROWSTR + ac[i] * 16, a_src[i] + kofs);
#pragma unroll
        for (int i = 0; i < 2; i++)
            cpasync16(sb + SB_OFF(buf) + br[i] * ROWSTR + bc[i] * 16, b_src[i] + kofs);
        if (tid < 256)
            cpasync16(sb + SB_OFF(buf) + br[2] * ROWSTR + bc[2] * 16, b_src[2] + kofs);
    };

    // ---- prologue: stages 0, 1 in flight
    issue_stage(0); cp_commit();
    issue_stage(1); cp_commit();

    float acc[4][5][4];
#pragma unroll
    for (int mt = 0; mt < 4; mt++)
#pragma unroll
        for (int nt = 0; nt < 5; nt++)
#pragma unroll
            for (int i = 0; i < 4; i++) acc[mt][nt][i] = 0.0f;

#pragma unroll 1
    for (int s = 0; s < NSTAGE; s++) {
        if (s + 1 < NSTAGE) cp_wait<1>(); else cp_wait<0>();
        __syncthreads();                 // stage s data visible to all warps

        const int buf = s & 1;
        const char* sa  = smem + SA_OFF(buf);
        const char* sbc = smem + SB_OFF(buf);

#pragma unroll
        for (int tp = 0; tp < 2; tp++) {   // each tp covers TWO k8 steps via one LDS.128 set
            float4 a0[4], a1[4];
#pragma unroll
            for (int mt = 0; mt < 4; mt++) {
                const char* abase = sa + (wm + mt * 16 + lg) * ROWSTR + tp * 64 + lt * 16;
                a0[mt] = *(const float4*)(abase);
                a1[mt] = *(const float4*)(abase + 8 * ROWSTR);
            }
#pragma unroll
            for (int nt = 0; nt < 5; nt++) {
                float4 bv = *(const float4*)(sbc + (wn + nt * 8 + lg) * ROWSTR + tp * 64 + lt * 16);
#pragma unroll
                for (int mt = 0; mt < 4; mt++) {
                    mma_tf32(acc[mt][nt], a0[mt].x, a1[mt].x, a0[mt].y, a1[mt].y, bv.x, bv.y);
                    mma_tf32(acc[mt][nt], a0[mt].z, a1[mt].z, a0[mt].w, a1[mt].w, bv.z, bv.w);
                }
            }
        }

        __syncthreads();                 // all warps done reading buf before overwrite
        if (s + 2 < NSTAGE) { issue_stage(s + 2); cp_commit(); }
    }

    // ---- scatter accumulators to gate buffer [5][256][34] (overlays pipeline SMEM)
    float* gsm = (float*)smem;
#pragma unroll
    for (int mt = 0; mt < 4; mt++) {
#pragma unroll
        for (int nt = 0; nt < 5; nt++) {
#pragma unroll
            for (int half = 0; half < 2; half++) {
                int row = wm + mt * 16 + lg + half * 8;
                int n   = wn + nt * 8 + lt * 2;
                int g = n >> 5, hc = n & 31;
                float2 v = make_float2(acc[mt][nt][half * 2], acc[mt][nt][half * 2 + 1]);
                *(float2*)&gsm[(g * BM + row) * GSTR + hc] = v;
            }
        }
    }
    __syncthreads();

    // ---- fused LSTM epilogue, fully coalesced global I/O
#pragma unroll 1
    for (int q = tid; q < BM * BHW; q += NTHREADS) {
        const int r = q >> 5, c = q & 31;
        const size_t gi = (size_t)(m0 + r) * HH + h0 + c;
        float gv_i = gsm[(0 * BM + r) * GSTR + c] + bias_s[0 * 32 + c];
        float gv_f = gsm[(1 * BM + r) * GSTR + c] + bias_s[1 * 32 + c];
        float gv_o = gsm[(2 * BM + r) * GSTR + c] + bias_s[2 * 32 + c];
        float gv_c = gsm[(3 * BM + r) * GSTR + c] + bias_s[3 * 32 + c];
        float gv_s = gsm[(4 * BM + r) * GSTR + c] + bias_s[4 * 32 + c];
        float i_t  = sigf(gv_i);
        float f_t  = sigf(gv_f);
        float o_t  = sigf(gv_o);
        float chat = tanhf(gv_c);
        float s_t  = sigf(gv_s) * dynw[gi];
        float c_t  = f_t * c_prev[gi] + i_t * chat * s_t;
        float h_t  = o_t * tanhf(c_t);
        out[gi] = h_t;
        out[OUT_C_OFF + gi] = c_t;
    }
}

// ---------------- launch ----------------
extern "C" void kernel_launch(void* const* d_in, const int* in_sizes, int n_in,
                              void* d_out, int out_size) {
    (void)in_sizes; (void)n_in; (void)out_size;
    const float* x  = (const float*)d_in[0];
    const float* hp = (const float*)d_in[1];
    const float* cp = (const float*)d_in[2];
    const float* dw = (const float*)d_in[3];
    const float* Wx = (const float*)d_in[4];
    const float* bx = (const float*)d_in[5];
    const float* Uh = (const float*)d_in[6];
    const float* bh = (const float*)d_in[7];
    float* out = (float*)d_out;

    conv_A<<<(BB * 512) / 256, 256>>>(x, hp);
    conv_W<<<(G5 * 512) / 256, 256>>>(Wx, Uh);
    conv_bias<<<(G5 + 255) / 256, 256>>>(bx, bh);

    cudaFuncSetAttribute(lstm_gemm, cudaFuncAttributeMaxDynamicSharedMemorySize, SMEM_TOTAL);
    dim3 grid(HH / BHW, BB / BM);   // (32, 64)
    lstm_gemm<<<grid, NTHREADS, SMEM_TOTAL>>>(cp, dw, out);
}

// round 15
// speedup vs baseline: 1.3693x; 1.3693x over previous
#include <cuda_runtime.h>
#include <cuda_bf16.h>
#include <cstdint>

// ---------------- problem constants ----------------
#define BB 16384
#define DD 1024
#define HH 1024
#define KK 2048          // D + H concatenated reduction dim
#define G5 5120          // 5 * H gate rows
#define OUT_C_OFF ((size_t)BB * HH)

// ---------------- GEMM tiling (tf32) ----------------
#define BM 128           // batch rows per CTA
#define BHW 32           // h columns per CTA (per gate)
#define BN 160           // 5 gates * 32 h
#define BK 32            // K elements per pipeline stage (128 B f32 per row)
#define NSTAGE (KK / BK) // 64
#define STAGES 3
#define NTHREADS 512     // 16 warps: 4(M) x 4(N), warp tile 32 x 40

// SMEM row: 128B data + 64B pad -> rows offset 64 mod 128 => conflict-free LDS.128
#define ROWSTR 192
#define SA_STAGE (BM * ROWSTR)             // 24576
#define SB_STAGE (BN * ROWSTR)             // 30720
#define SA_OFF(s) ((s) * SA_STAGE)
#define SB_OFF(s) (STAGES * SA_STAGE + (s) * SB_STAGE)
#define PIPE_BYTES (STAGES * (SA_STAGE + SB_STAGE))      // 165888
// epilogue gate buffer [5][128][34] floats overlays pipeline region (87040 B)
#define GSTR 34
#define SM_BIAS PIPE_BYTES                 // 160 floats after pipeline region
#define SMEM_TOTAL (PIPE_BYTES + 1024)     // 166912

// ---------------- device scratch (allocation-free) ----------------
// k-dimension stored PERMUTED within each 16-k block:
//   stored position p holds original k = (p&3)*4 + (p>>2)
// so positions 4*lt .. 4*lt+3 hold original k {lt, lt+4, lt+8, lt+12}
__device__ float g_A[(size_t)BB * KK];   // 134 MB  [x | h_prev], tf32-rounded f32
__device__ float g_W[(size_t)G5 * KK];   //  42 MB  [Wx | Uh],    tf32-rounded f32
__device__ float g_bias[G5];

// ---------------- PTX helpers (base-target only: sm_80+) ----------------
__device__ __forceinline__ void cpasync16(uint32_t dst, const void* src) {
    asm volatile("cp.async.cg.shared.global [%0], [%1], 16;" :: "r"(dst), "l"(src) : "memory");
}
__device__ __forceinline__ void cp_commit() {
    asm volatile("cp.async.commit_group;" ::: "memory");
}
template <int N>
__device__ __forceinline__ void cp_wait() {
    asm volatile("cp.async.wait_group %0;" :: "n"(N) : "memory");
}
__device__ __forceinline__ uint32_t smem_u32(const void* p) {
    uint32_t a;
    asm("{ .reg .u64 t; cvta.to.shared.u64 t, %1; cvt.u32.u64 %0, t; }" : "=r"(a) : "l"(p));
    return a;
}
// round-to-nearest tf32 (clears low 13 mantissa bits with rna rounding)
__device__ __forceinline__ float rna_tf32(float x) {
    uint32_t u;
    asm("cvt.rna.tf32.f32 %0, %1;" : "=r"(u) : "f"(x));
    return __uint_as_float(u);
}
__device__ __forceinline__ void mma_tf32(float* d,
                                         float a0, float a1, float a2, float a3,
                                         float b0, float b1) {
    asm volatile(
        "mma.sync.aligned.m16n8k8.row.col.f32.tf32.tf32.f32 "
        "{%0,%1,%2,%3}, {%4,%5,%6,%7}, {%8,%9}, {%0,%1,%2,%3};"
        : "+f"(d[0]), "+f"(d[1]), "+f"(d[2]), "+f"(d[3])
        : "r"(__float_as_uint(a0)), "r"(__float_as_uint(a1)),
          "r"(__float_as_uint(a2)), "r"(__float_as_uint(a3)),
          "r"(__float_as_uint(b0)), "r"(__float_as_uint(b1)));
}
__device__ __forceinline__ float sigf(float v) { return 1.0f / (1.0f + __expf(-v)); }

// ---------------- convert kernels (concat + rna round + k16 permute) ----------------
__global__ void conv_A(const float* __restrict__ x, const float* __restrict__ hp) {
    int gid = blockIdx.x * blockDim.x + threadIdx.x;   // BB*512 threads, float4 each
    int b = gid >> 9, rem = gid & 511;
    const float* src = (rem < 256) ? (x + (size_t)b * 1024 + rem * 4)
                                   : (hp + (size_t)b * 1024 + (rem - 256) * 4);
    float4 v = *(const float4*)src;
    float* dst = g_A + (size_t)b * KK + ((rem >> 2) << 4) + (rem & 3);
    dst[0]  = rna_tf32(v.x);
    dst[4]  = rna_tf32(v.y);
    dst[8]  = rna_tf32(v.z);
    dst[12] = rna_tf32(v.w);
}
__global__ void conv_W(const float* __restrict__ Wx, const float* __restrict__ Uh) {
    int gid = blockIdx.x * blockDim.x + threadIdx.x;   // G5*512 threads
    int r = gid >> 9, rem = gid & 511;
    const float* src = (rem < 256) ? (Wx + (size_t)r * 1024 + rem * 4)
                                   : (Uh + (size_t)r * 1024 + (rem - 256) * 4);
    float4 v = *(const float4*)src;
    float* dst = g_W + (size_t)r * KK + ((rem >> 2) << 4) + (rem & 3);
    dst[0]  = rna_tf32(v.x);
    dst[4]  = rna_tf32(v.y);
    dst[8]  = rna_tf32(v.z);
    dst[12] = rna_tf32(v.w);
}
__global__ void conv_bias(const float* __restrict__ bx, const float* __restrict__ bh) {
    int i = blockIdx.x * blockDim.x + threadIdx.x;
    if (i < G5) g_bias[i] = bx[i] + bh[i];
}

// ---------------- fused GEMM (mma.sync tf32) + LSTM epilogue ----------------
__global__ void __launch_bounds__(NTHREADS, 1)
lstm_gemm(const float* __restrict__ c_prev, const float* __restrict__ dynw,
          float* __restrict__ out) {
    extern __shared__ char smem[];
    const uint32_t sb = smem_u32(smem);
    const int tid  = threadIdx.x;
    const int wid  = tid >> 5;
    const int lane = tid & 31;
    const int h0 = blockIdx.x * BHW;     // 32 h-blocks (x fastest -> A-tile L2 reuse)
    const int m0 = blockIdx.y * BM;      // 128 m-blocks

    // warp grid 4(M) x 4(N): warp tile 32 x 40
    const int wm = (wid >> 2) * 32;
    const int wn = (wid & 3) * 40;
    const int lg = lane >> 2;            // fragment row group 0..7
    const int lt = lane & 3;             // fragment k selector 0..3
    const int tpo = wid & 1;             // warp-phase stagger: half the warps start at tp=1

    // bias staging (region beyond pipeline buffers)
    float* bias_s = (float*)(smem + SM_BIAS);
    if (tid < BN) bias_s[tid] = g_bias[(tid >> 5) * 1024 + h0 + (tid & 31)];

    // ---- per-thread cp.async assignments (fixed across stages)
    // A: 128 rows x 8 chunks(16B) = 1024 -> 2 per thread
    const int a0q = tid, a1q = 512 + tid;
    const int a0r = a0q >> 3, a0c = a0q & 7;
    const int a1r = a1q >> 3, a1c = a1q & 7;
    const float* a_src0 = g_A + (size_t)(m0 + a0r) * KK + a0c * 4;
    const float* a_src1 = g_A + (size_t)(m0 + a1r) * KK + a1c * 4;
    // B: 160 rows x 8 chunks = 1280 -> 2 per thread + 1 extra for tid<256
    const int b0q = tid, b1q = 512 + tid, b2q = 1024 + tid;
    const int b0r = b0q >> 3, b0c = b0q & 7;
    const int b1r = b1q >> 3, b1c = b1q & 7;
    const int b2r = b2q >> 3, b2c = b2q & 7;
    const float* b_src0 = g_W + (size_t)((b0r >> 5) * 1024 + h0 + (b0r & 31)) * KK + b0c * 4;
    const float* b_src1 = g_W + (size_t)((b1r >> 5) * 1024 + h0 + (b1r & 31)) * KK + b1c * 4;
    const float* b_src2 = g_W + (size_t)((b2r >> 5) * 1024 + h0 + (b2r & 31)) * KK + b2c * 4;

    auto issue_stage = [&](int s) {
        const int buf = s % STAGES;
        const int kofs = s * BK;
        cpasync16(sb + SA_OFF(buf) + a0r * ROWSTR + a0c * 16, a_src0 + kofs);
        cpasync16(sb + SA_OFF(buf) + a1r * ROWSTR + a1c * 16, a_src1 + kofs);
        cpasync16(sb + SB_OFF(buf) + b0r * ROWSTR + b0c * 16, b_src0 + kofs);
        cpasync16(sb + SB_OFF(buf) + b1r * ROWSTR + b1c * 16, b_src1 + kofs);
        if (tid < 256)
            cpasync16(sb + SB_OFF(buf) + b2r * ROWSTR + b2c * 16, b_src2 + kofs);
    };

    // ---- prologue: stages 0, 1
    issue_stage(0); cp_commit();
    issue_stage(1); cp_commit();

    float acc[2][5][4];
#pragma unroll
    for (int mt = 0; mt < 2; mt++)
#pragma unroll
        for (int nt = 0; nt < 5; nt++)
#pragma unroll
            for (int i = 0; i < 4; i++) acc[mt][nt][i] = 0.0f;

#pragma unroll 1
    for (int s = 0; s < NSTAGE; s++) {
        if (s + 1 < NSTAGE) cp_wait<1>(); else cp_wait<0>();
        __syncthreads();                 // stage s visible; all warps done with stage s-1
        if (s + 2 < NSTAGE) { issue_stage(s + 2); cp_commit(); }

        const int buf = s % STAGES;
        const char* sa  = smem + SA_OFF(buf);
        const char* sbc = smem + SB_OFF(buf);

#pragma unroll
        for (int i = 0; i < 2; i++) {
            // warp-staggered phase: even warps do tp=0,1; odd warps tp=1,0.
            // At any instant half the warps are in LDS phase, half in MMA phase,
            // so the shared crossbar and the tensor pipe overlap instead of
            // serializing (R9 measured them perfectly serialized: 1280+1152 cyc).
            const int tp = tpo ^ i;
            float4 av[2][2];
#pragma unroll
            for (int mt = 0; mt < 2; mt++) {
                av[mt][0] = *(const float4*)(sa + (wm + mt * 16 + lg) * ROWSTR + tp * 64 + lt * 16);
                av[mt][1] = *(const float4*)(sa + (wm + mt * 16 + lg + 8) * ROWSTR + tp * 64 + lt * 16);
            }
            float4 bv[5];
#pragma unroll
            for (int nt = 0; nt < 5; nt++)
                bv[nt] = *(const float4*)(sbc + (wn + nt * 8 + lg) * ROWSTR + tp * 64 + lt * 16);

#pragma unroll
            for (int mt = 0; mt < 2; mt++)
#pragma unroll
                for (int nt = 0; nt < 5; nt++) {
                    mma_tf32(acc[mt][nt], av[mt][0].x, av[mt][1].x, av[mt][0].y, av[mt][1].y,
                             bv[nt].x, bv[nt].y);
                    mma_tf32(acc[mt][nt], av[mt][0].z, av[mt][1].z, av[mt][0].w, av[mt][1].w,
                             bv[nt].z, bv[nt].w);
                }
        }
    }

    __syncthreads();   // all warps done reading pipeline SMEM before reuse

    // ---- scatter accumulators to gate buffer [5][128][34] (overlays pipeline SMEM)
    float* gsm = (float*)smem;
#pragma unroll
    for (int mt = 0; mt < 2; mt++) {
#pragma unroll
        for (int nt = 0; nt < 5; nt++) {
#pragma unroll
            for (int half = 0; half < 2; half++) {
                int row = wm + mt * 16 + lg + half * 8;
                int n   = wn + nt * 8 + lt * 2;
                int g = n >> 5, hc = n & 31;
                float2 v = make_float2(acc[mt][nt][half * 2], acc[mt][nt][half * 2 + 1]);
                *(float2*)&gsm[(g * BM + row) * GSTR + hc] = v;
            }
        }
    }
    __syncthreads();

    // ---- fused LSTM epilogue, fully coalesced global I/O
#pragma unroll 1
    for (int q = tid; q < BM * BHW; q += NTHREADS) {
        const int r = q >> 5, c = q & 31;
        const size_t gi = (size_t)(m0 + r) * HH + h0 + c;
        float gv_i = gsm[(0 * BM + r) * GSTR + c] + bias_s[0 * 32 + c];
        float gv_f = gsm[(1 * BM + r) * GSTR + c] + bias_s[1 * 32 + c];
        float gv_o = gsm[(2 * BM + r) * GSTR + c] + bias_s[2 * 32 + c];
        float gv_c = gsm[(3 * BM + r) * GSTR + c] + bias_s[3 * 32 + c];
        float gv_s = gsm[(4 * BM + r) * GSTR + c] + bias_s[4 * 32 + c];
        float i_t  = sigf(gv_i);
        float f_t  = sigf(gv_f);
        float o_t  = sigf(gv_o);
        float chat = tanhf(gv_c);
        float s_t  = sigf(gv_s) * dynw[gi];
        float c_t  = f_t * c_prev[gi] + i_t * chat * s_t;
        float h_t  = o_t * tanhf(c_t);
        out[gi] = h_t;
        out[OUT_C_OFF + gi] = c_t;
    }
}

// ---------------- launch ----------------
extern "C" void kernel_launch(void* const* d_in, const int* in_sizes, int n_in,
                              void* d_out, int out_size) {
    (void)in_sizes; (void)n_in; (void)out_size;
    const float* x  = (const float*)d_in[0];
    const float* hp = (const float*)d_in[1];
    const float* cp = (const float*)d_in[2];
    const float* dw = (const float*)d_in[3];
    const float* Wx = (const float*)d_in[4];
    const float* bx = (const float*)d_in[5];
    const float* Uh = (const float*)d_in[6];
    const float* bh = (const float*)d_in[7];
    float* out = (float*)d_out;

    conv_A<<<(BB * 512) / 256, 256>>>(x, hp);
    conv_W<<<(G5 * 512) / 256, 256>>>(Wx, Uh);
    conv_bias<<<(G5 + 255) / 256, 256>>>(bx, bh);

    cudaFuncSetAttribute(lstm_gemm, cudaFuncAttributeMaxDynamicSharedMemorySize, SMEM_TOTAL);
    dim3 grid(HH / BHW, BB / BM);   // (32, 128)
    lstm_gemm<<<grid, NTHREADS, SMEM_TOTAL>>>(cp, dw, out);
}